// round 6
// baseline (speedup 1.0000x reference)
#include <cuda_runtime.h>
#include <cuda_bf16.h>
#include <cstdint>

#define BB 8
#define SS 4096
#define TT 512
#define HH 768

// ---------------------------------------------------------------------------
// Scratch (device .bss). Split bf16 operands: [R, 2C], hi in [0,C), lo in [C,2C).
// ---------------------------------------------------------------------------
__device__ __align__(16) __nv_bfloat16 g_seq2 [(size_t)BB * SS * 2 * HH];
__device__ __align__(16) __nv_bfloat16 g_tgt2 [(size_t)BB * TT * 2 * HH];
__device__ __align__(16) __nv_bfloat16 g_W2   [(size_t)HH * 2 * HH];
__device__ __align__(16) __nv_bfloat16 g_seqt2[(size_t)BB * SS * 2 * HH];
__device__ __align__(16) __nv_bfloat16 g_tgtt2[(size_t)BB * TT * 2 * HH];
__device__ __align__(16) float         g_logits[(size_t)BB * SS * TT];
__device__ __align__(16) __nv_bfloat16 g_probs2[(size_t)BB * SS * 2 * TT];
__device__ __align__(16) __nv_bfloat16 g_vT2  [(size_t)BB * HH * 2 * TT];  // [B, H, 2T]

// ---------------------------------------------------------------------------
// Helpers (baseline PTX: cp.async / ldmatrix / mma.sync — sm_80+ ISA)
// ---------------------------------------------------------------------------
__device__ __forceinline__ uint32_t smem_u32(const void* p) {
    uint32_t a;
    asm("{ .reg .u64 t; cvta.to.shared.u64 t, %1; cvt.u32.u64 %0, t; }" : "=r"(a) : "l"(p));
    return a;
}
__device__ __forceinline__ void cp16(uint32_t saddr, const void* g) {
    asm volatile("cp.async.cg.shared.global [%0], [%1], 16;" :: "r"(saddr), "l"(g) : "memory");
}
#define CP_COMMIT() asm volatile("cp.async.commit_group;" ::: "memory")
template <int N>
__device__ __forceinline__ void cp_wait() {
    asm volatile("cp.async.wait_group %0;" :: "n"(N) : "memory");
}
__device__ __forceinline__ void ldsm_x4(uint32_t* r, uint32_t addr) {
    asm volatile("ldmatrix.sync.aligned.m8n8.x4.shared.b16 {%0,%1,%2,%3}, [%4];"
        : "=r"(r[0]), "=r"(r[1]), "=r"(r[2]), "=r"(r[3]) : "r"(addr));
}
__device__ __forceinline__ void mma_bf16(float* c, const uint32_t* a, const uint32_t* b) {
    asm volatile(
        "mma.sync.aligned.m16n8k16.row.col.f32.bf16.bf16.f32 "
        "{%0,%1,%2,%3}, {%4,%5,%6,%7}, {%8,%9}, {%0,%1,%2,%3};"
        : "+f"(c[0]), "+f"(c[1]), "+f"(c[2]), "+f"(c[3])
        : "r"(a[0]), "r"(a[1]), "r"(a[2]), "r"(a[3]), "r"(b[0]), "r"(b[1]));
}
__device__ __forceinline__ void split1(float x, __nv_bfloat16& h, __nv_bfloat16& l) {
    h = __float2bfloat16(x);
    l = __float2bfloat16(x - __bfloat162float(h));
}

// ---------------------------------------------------------------------------
// HMMA GEMM: D = Ahi*Bhi + Alo*Bhi + Ahi*Blo (split-bf16 3-term).
// A: [rows, 2C] split bf16 K-major. B: [N, 2C] split bf16 K-major.
// CTA tile 128x256, BK=64, 3-buffer cp.async (2-ahead prefetch),
// 256 threads = 8 warps (2m x 4n), warp tile 64x64.
// smem/stage: A 16KB + B 32KB = 48KB; 3 stages = 144KB.
// EPI: 0 = relu + split-bf16; 1 = fp32; 2 = attn/cat.
// ---------------------------------------------------------------------------
template <int EPI>
__launch_bounds__(256, 1)
__global__ void gemm_mma(const __nv_bfloat16* __restrict__ A,
                         const __nv_bfloat16* __restrict__ Bm,
                         long aBatch, long bBatch, int C,
                         float* __restrict__ out0, float* __restrict__ out1,
                         __nv_bfloat16* __restrict__ obf,
                         const int* __restrict__ smask, int writeAttn)
{
    extern __shared__ char smem[];
    const uint32_t sb = smem_u32(smem);

    const int tid = threadIdx.x;
    const int wid = tid >> 5;
    const int lane = tid & 31;

    const int z = blockIdx.z;
    const int m0 = blockIdx.y * 128;
    const int n0 = blockIdx.x * 256;
    const long Kr = 2L * C;
    const __nv_bfloat16* Ab = A + (long)z * aBatch;
    const __nv_bfloat16* Bb = Bm + (long)z * bBatch;

    const int kc = C >> 6;     // 64-col chunks per segment
    const int nk = 3 * kc;

    const int vr0 = tid >> 3;          // load row base (stride 32)
    const int vc16 = (tid & 7) * 16;   // byte offset in 128B row

#define LDG_STAGE(IT, S)                                                          \
    {                                                                             \
        int _it = (IT);                                                           \
        int _seg = (_it >= 2 * kc) ? 2 : ((_it >= kc) ? 1 : 0);                   \
        int _kl = _it - _seg * kc;                                                \
        long _aC = ((_seg == 1) ? C : 0) + (long)_kl * 64 + (vc16 >> 1);          \
        long _bC = ((_seg == 2) ? C : 0) + (long)_kl * 64 + (vc16 >> 1);          \
        uint32_t _sA = sb + (S) * 49152u;                                         \
        uint32_t _sB = _sA + 16384u;                                              \
        _Pragma("unroll")                                                         \
        for (int i = 0; i < 4; i++) {                                             \
            int r = vr0 + 32 * i;                                                 \
            uint32_t sw = (uint32_t)(r * 128 + (vc16 ^ ((r & 7) << 4)));          \
            cp16(_sA + sw, Ab + (long)(m0 + r) * Kr + _aC);                       \
        }                                                                         \
        _Pragma("unroll")                                                         \
        for (int i = 0; i < 8; i++) {                                             \
            int r = vr0 + 32 * i;                                                 \
            uint32_t sw = (uint32_t)(r * 128 + (vc16 ^ ((r & 7) << 4)));          \
            cp16(_sB + sw, Bb + (long)(n0 + r) * Kr + _bC);                       \
        }                                                                         \
    }

    // prologue: prefetch stages 0,1 into buffers 0,1 (buffer 2 free)
    LDG_STAGE(0, 0); CP_COMMIT();
    LDG_STAGE(1, 1); CP_COMMIT();

    const int wm = wid & 1;     // 0..1 -> 64 rows
    const int wn = wid >> 1;    // 0..3 -> 64 cols

    float acc[4][8][4] = {};

    const int arow = wm * 64 + (lane & 15);                     // + mt*16
    const int akb = (lane >> 4) * 16;
    const int brow = wn * 64 + (lane & 7) + ((lane >> 4) * 8);  // + ntp*16
    const int bkb = ((lane >> 3) & 1) * 16;

    for (int it = 0; it < nk; it++) {
        if (it + 2 < nk)      { LDG_STAGE(it + 2, (it + 2) % 3); CP_COMMIT(); cp_wait<2>(); }
        else if (it + 1 < nk) { cp_wait<1>(); }
        else                  { cp_wait<0>(); }
        __syncthreads();

        const uint32_t stA = sb + (uint32_t)(it % 3) * 49152u;
        const uint32_t stB = stA + 16384u;

        #pragma unroll
        for (int ks = 0; ks < 4; ks++) {
            uint32_t afr[4][4], bfr[4][4];
            #pragma unroll
            for (int mt = 0; mt < 4; mt++) {
                const int row = arow + mt * 16;
                ldsm_x4(afr[mt], stA + row * 128 + ((ks * 32 + akb) ^ ((row & 7) << 4)));
            }
            #pragma unroll
            for (int ntp = 0; ntp < 4; ntp++) {
                const int row = brow + ntp * 16;
                ldsm_x4(bfr[ntp], stB + row * 128 + ((ks * 32 + bkb) ^ ((row & 7) << 4)));
            }
            #pragma unroll
            for (int mt = 0; mt < 4; mt++)
                #pragma unroll
                for (int nt = 0; nt < 8; nt++)
                    mma_bf16(acc[mt][nt], afr[mt], &bfr[nt >> 1][(nt & 1) * 2]);
        }
        __syncthreads();
    }

    // ---- epilogue ----
    const int er = wm * 64 + (lane >> 2);        // + mt*16 (+8 for c2/c3)
    const int ec = wn * 64 + (lane & 3) * 2;     // + nt*8

    if (EPI == 0) {
        const int Nout = gridDim.x * 256;
        #pragma unroll
        for (int mt = 0; mt < 4; mt++)
            #pragma unroll
            for (int nt = 0; nt < 8; nt++)
                #pragma unroll
                for (int h = 0; h < 2; h++) {
                    const int row = m0 + er + mt * 16 + h * 8;
                    const int col = n0 + ec + nt * 8;
                    float x0 = fmaxf(acc[mt][nt][2 * h], 0.f);
                    float x1 = fmaxf(acc[mt][nt][2 * h + 1], 0.f);
                    __nv_bfloat16 h0, l0, h1, l1;
                    split1(x0, h0, l0); split1(x1, h1, l1);
                    __nv_bfloat16* oh = obf + (long)row * 2 * Nout + col;
                    *reinterpret_cast<__nv_bfloat162*>(oh) = __nv_bfloat162(h0, h1);
                    *reinterpret_cast<__nv_bfloat162*>(oh + Nout) = __nv_bfloat162(l0, l1);
                }
    } else if (EPI == 1) {
        #pragma unroll
        for (int mt = 0; mt < 4; mt++)
            #pragma unroll
            for (int nt = 0; nt < 8; nt++)
                #pragma unroll
                for (int h = 0; h < 2; h++) {
                    const int row = m0 + er + mt * 16 + h * 8;
                    const int col = n0 + ec + nt * 8;
                    float2 v = make_float2(acc[mt][nt][2 * h], acc[mt][nt][2 * h + 1]);
                    *reinterpret_cast<float2*>(out0 + ((long)z * SS + row) * TT + col) = v;
                }
    } else {
        #pragma unroll
        for (int mt = 0; mt < 4; mt++)
            #pragma unroll
            for (int nt = 0; nt < 8; nt++)
                #pragma unroll
                for (int h = 0; h < 2; h++) {
                    const int row = m0 + er + mt * 16 + h * 8;
                    const int col = n0 + ec + nt * 8;
                    const long gs = (long)z * SS + row;
                    const float m = (float)smask[gs];
                    float2 v = make_float2(acc[mt][nt][2 * h], acc[mt][nt][2 * h + 1]);
                    if (writeAttn)
                        *reinterpret_cast<float2*>(out1 + gs * (long)HH + col) = v;
                    float2 vm = make_float2(v.x * m, v.y * m);
                    *reinterpret_cast<float2*>(out0 + gs * (long)(2 * HH) + HH + col) = vm;
                }
    }
#undef LDG_STAGE
}

// ---------------------------------------------------------------------------
// fp32 [R,C] (row-masked) -> split bf16 [R,2C]; optionally also writes the
// masked fp32 row into out_cat[row, 0:C] (cat first half, stride 2C).
// ---------------------------------------------------------------------------
__launch_bounds__(256)
__global__ void split_mask(const float* __restrict__ in, const int* __restrict__ mask,
                           __nv_bfloat16* __restrict__ out, float* __restrict__ cat,
                           int R, int C)
{
    const long idx = (long)blockIdx.x * blockDim.x + threadIdx.x;  // float4 units
    const long total = (long)R * C / 4;
    if (idx >= total) return;
    const long row = idx / (C / 4);
    const int c4 = (int)(idx % (C / 4));
    const float m = mask ? (float)mask[row] : 1.0f;
    float4 v = reinterpret_cast<const float4*>(in)[idx];
    v.x *= m; v.y *= m; v.z *= m; v.w *= m;
    __nv_bfloat16 h0, l0, h1, l1, h2, l2, h3, l3;
    split1(v.x, h0, l0); split1(v.y, h1, l1); split1(v.z, h2, l2); split1(v.w, h3, l3);
    __nv_bfloat16* oh = out + row * 2L * C + c4 * 4;
    __nv_bfloat16* ol = oh + C;
    reinterpret_cast<__nv_bfloat162*>(oh)[0] = __nv_bfloat162(h0, h1);
    reinterpret_cast<__nv_bfloat162*>(oh)[1] = __nv_bfloat162(h2, h3);
    reinterpret_cast<__nv_bfloat162*>(ol)[0] = __nv_bfloat162(l0, l1);
    reinterpret_cast<__nv_bfloat162*>(ol)[1] = __nv_bfloat162(l2, l3);
    if (cat)
        reinterpret_cast<float4*>(cat)[row * (long)(2 * C / 4) + c4] = v;
}

// ---------------------------------------------------------------------------
// V^T split: O[b,h,t] = split(V[b,t,h]);  O layout [B, H, 2T]
// ---------------------------------------------------------------------------
__global__ void vT_split(const float* __restrict__ V, __nv_bfloat16* __restrict__ O)
{
    __shared__ float tile[32][33];
    const int b = blockIdx.z;
    const int t0 = blockIdx.x * 32, h0 = blockIdx.y * 32;
    const int tx = threadIdx.x, ty = threadIdx.y;  // 32 x 8
    #pragma unroll
    for (int i = 0; i < 32; i += 8)
        tile[ty + i][tx] = V[((long)b * TT + t0 + ty + i) * HH + h0 + tx];
    __syncthreads();
    #pragma unroll
    for (int i = 0; i < 32; i += 8) {
        const int h = h0 + ty + i, t = t0 + tx;
        __nv_bfloat16 hh, ll;
        split1(tile[tx][ty + i], hh, ll);
        const long base = ((long)b * HH + h) * (2L * TT) + t;
        O[base] = hh; O[base + TT] = ll;
    }
}

// ---------------------------------------------------------------------------
// Row softmax over T=512 + split-bf16 probs write.
// ---------------------------------------------------------------------------
__launch_bounds__(128)
__global__ void softmax_split(const float* __restrict__ logits, __nv_bfloat16* __restrict__ P2)
{
    const long row = blockIdx.x;
    const float* p = logits + row * TT;
    const int tid = threadIdx.x;
    const int warp = tid >> 5, lane = tid & 31;

    float v[4];
    #pragma unroll
    for (int i = 0; i < 4; i++) v[i] = p[tid + 128 * i];

    float mx = fmaxf(fmaxf(v[0], v[1]), fmaxf(v[2], v[3]));
    #pragma unroll
    for (int o = 16; o > 0; o >>= 1) mx = fmaxf(mx, __shfl_xor_sync(0xffffffffu, mx, o));
    __shared__ float smx[4];
    if (lane == 0) smx[warp] = mx;
    __syncthreads();
    mx = fmaxf(fmaxf(smx[0], smx[1]), fmaxf(smx[2], smx[3]));

    float sum = 0.f;
    #pragma unroll
    for (int i = 0; i < 4; i++) { v[i] = __expf(v[i] - mx); sum += v[i]; }
    #pragma unroll
    for (int o = 16; o > 0; o >>= 1) sum += __shfl_xor_sync(0xffffffffu, sum, o);
    __shared__ float ssum[4];
    if (lane == 0) ssum[warp] = sum;
    __syncthreads();
    const float inv = 1.0f / (ssum[0] + ssum[1] + ssum[2] + ssum[3]);

    __nv_bfloat16* out = P2 + row * 2L * TT;
    #pragma unroll
    for (int i = 0; i < 4; i++) {
        const int idx = tid + 128 * i;
        __nv_bfloat16 h, l;
        split1(v[i] * inv, h, l);
        out[idx] = h; out[TT + idx] = l;
    }
}

// ---------------------------------------------------------------------------

extern "C" void kernel_launch(void* const* d_in, const int* in_sizes, int n_in,
                              void* d_out, int out_size)
{
    const float* seq   = (const float*)d_in[0];
    const int*   smask = (const int*)d_in[1];
    const float* tgt   = (const float*)d_in[2];
    const int*   tmask = (const int*)d_in[3];
    const float* W     = (const float*)d_in[4];
    float* out = (float*)d_out;

    __nv_bfloat16 *p_seq2, *p_tgt2, *p_W2, *p_seqt2, *p_tgtt2, *p_probs2, *p_vT2;
    float* p_logits;
    cudaGetSymbolAddress((void**)&p_seq2, g_seq2);
    cudaGetSymbolAddress((void**)&p_tgt2, g_tgt2);
    cudaGetSymbolAddress((void**)&p_W2, g_W2);
    cudaGetSymbolAddress((void**)&p_seqt2, g_seqt2);
    cudaGetSymbolAddress((void**)&p_tgtt2, g_tgtt2);
    cudaGetSymbolAddress((void**)&p_logits, g_logits);
    cudaGetSymbolAddress((void**)&p_probs2, g_probs2);
    cudaGetSymbolAddress((void**)&p_vT2, g_vT2);

    const int write_attn = (out_size >= BB * SS * 3 * HH) ? 1 : 0;
    float* out_attn = out + (size_t)BB * SS * 2 * HH;

    const int SMEM_DYN = 3 * 49152;  // 147456
    cudaFuncSetAttribute(gemm_mma<0>, cudaFuncAttributeMaxDynamicSharedMemorySize, SMEM_DYN);
    cudaFuncSetAttribute(gemm_mma<1>, cudaFuncAttributeMaxDynamicSharedMemorySize, SMEM_DYN);
    cudaFuncSetAttribute(gemm_mma<2>, cudaFuncAttributeMaxDynamicSharedMemorySize, SMEM_DYN);

    // 0) operand conversions (seq variant also writes cat first half)
    split_mask<<<(BB * SS * HH / 4 + 255) / 256, 256>>>(seq, smask, p_seq2, out, BB * SS, HH);
    split_mask<<<(BB * TT * HH / 4 + 255) / 256, 256>>>(tgt, tmask, p_tgt2, nullptr, BB * TT, HH);
    split_mask<<<(HH * HH / 4 + 255) / 256, 256>>>(W, nullptr, p_W2, nullptr, HH, HH);
    vT_split<<<dim3(TT / 32, HH / 32, BB), dim3(32, 8)>>>(tgt, p_vT2);

    // 1) seq_t = relu((seq*sm) @ W^T)  -> split bf16
    gemm_mma<0><<<dim3(HH / 256, (BB * SS) / 128, 1), 256, SMEM_DYN>>>(
        p_seq2, p_W2, 0, 0, HH, nullptr, nullptr, p_seqt2, nullptr, 0);

    // 2) tgt_t = relu((tgt*tm) @ W^T)  -> split bf16
    gemm_mma<0><<<dim3(HH / 256, (BB * TT) / 128, 1), 256, SMEM_DYN>>>(
        p_tgt2, p_W2, 0, 0, HH, nullptr, nullptr, p_tgtt2, nullptr, 0);

    // 3) logits[b] = seq_t[b] @ tgt_t[b]^T  -> fp32
    gemm_mma<1><<<dim3(TT / 256, SS / 128, BB), 256, SMEM_DYN>>>(
        p_seqt2, p_tgtt2, (long)SS * 2 * HH, (long)TT * 2 * HH, HH,
        p_logits, nullptr, nullptr, nullptr, 0);

    // 4) softmax + split
    softmax_split<<<BB * SS, 128>>>(p_logits, p_probs2);

    // 5) attn_out = P @ V^T-split, fused cat/attn epilogue
    gemm_mma<2><<<dim3(HH / 256, SS / 128, BB), 256, SMEM_DYN>>>(
        p_probs2, p_vT2, (long)SS * 2 * TT, (long)HH * 2 * TT, TT,
        out, out_attn, nullptr, smask, write_attn);
}

// round 7
// speedup vs baseline: 1.2136x; 1.2136x over previous
#include <cuda_runtime.h>
#include <cuda_bf16.h>
#include <cstdint>

#define BB 8
#define SS 4096
#define TT 512
#define HH 768

// ---------------------------------------------------------------------------
// Scratch (device .bss). Split bf16 operands: [R, 2C], hi in [0,C), lo in [C,2C).
// ---------------------------------------------------------------------------
__device__ __align__(16) __nv_bfloat16 g_seq2 [(size_t)BB * SS * 2 * HH];
__device__ __align__(16) __nv_bfloat16 g_tgt2 [(size_t)BB * TT * 2 * HH];
__device__ __align__(16) __nv_bfloat16 g_W2   [(size_t)HH * 2 * HH];
__device__ __align__(16) __nv_bfloat16 g_seqt2[(size_t)BB * SS * 2 * HH];
__device__ __align__(16) __nv_bfloat16 g_tgtt2[(size_t)BB * TT * 2 * HH];
__device__ __align__(16) float         g_logits[(size_t)BB * SS * TT];
__device__ __align__(16) __nv_bfloat16 g_probs2[(size_t)BB * SS * 2 * TT];
__device__ __align__(16) __nv_bfloat16 g_vT2  [(size_t)BB * HH * 2 * TT];  // [B, H, 2T]

// ---------------------------------------------------------------------------
// Helpers (baseline PTX: cp.async / ldmatrix / mma.sync — sm_80+ ISA)
// ---------------------------------------------------------------------------
__device__ __forceinline__ uint32_t smem_u32(const void* p) {
    uint32_t a;
    asm("{ .reg .u64 t; cvta.to.shared.u64 t, %1; cvt.u32.u64 %0, t; }" : "=r"(a) : "l"(p));
    return a;
}
__device__ __forceinline__ void cp16(uint32_t saddr, const void* g) {
    asm volatile("cp.async.cg.shared.global [%0], [%1], 16;" :: "r"(saddr), "l"(g) : "memory");
}
#define CP_COMMIT() asm volatile("cp.async.commit_group;" ::: "memory")
template <int N>
__device__ __forceinline__ void cp_wait() {
    asm volatile("cp.async.wait_group %0;" :: "n"(N) : "memory");
}
__device__ __forceinline__ void ldsm_x4(uint32_t* r, uint32_t addr) {
    asm volatile("ldmatrix.sync.aligned.m8n8.x4.shared.b16 {%0,%1,%2,%3}, [%4];"
        : "=r"(r[0]), "=r"(r[1]), "=r"(r[2]), "=r"(r[3]) : "r"(addr));
}
__device__ __forceinline__ void mma_bf16(float* c, const uint32_t* a, const uint32_t* b) {
    asm volatile(
        "mma.sync.aligned.m16n8k16.row.col.f32.bf16.bf16.f32 "
        "{%0,%1,%2,%3}, {%4,%5,%6,%7}, {%8,%9}, {%0,%1,%2,%3};"
        : "+f"(c[0]), "+f"(c[1]), "+f"(c[2]), "+f"(c[3])
        : "r"(a[0]), "r"(a[1]), "r"(a[2]), "r"(a[3]), "r"(b[0]), "r"(b[1]));
}
__device__ __forceinline__ void split1(float x, __nv_bfloat16& h, __nv_bfloat16& l) {
    h = __float2bfloat16(x);
    l = __float2bfloat16(x - __bfloat162float(h));
}

// ---------------------------------------------------------------------------
// HMMA GEMM: D = Ahi*Bhi + Alo*Bhi + Ahi*Blo (split-bf16 3-term).
// A: [rows, 2C] split bf16 K-major. B: [N, 2C] split bf16 K-major.
// CTA tile 128x128, BK=64, 3-buffer cp.async, ONE sync per iteration
// (wait -> sync -> compute -> prefetch it+2; barrier proves stage it-1
// reads are done before its buffer is overwritten).
// 256 threads = 8 warps (2m x 4n), warp tile 64x32. smem 96KB -> 2 CTAs/SM.
// EPI: 0 = relu + split-bf16; 1 = fp32; 2 = attn/cat.
// ---------------------------------------------------------------------------
template <int EPI>
__launch_bounds__(256)
__global__ void gemm_mma(const __nv_bfloat16* __restrict__ A,
                         const __nv_bfloat16* __restrict__ Bm,
                         long aBatch, long bBatch, int C,
                         float* __restrict__ out0, float* __restrict__ out1,
                         __nv_bfloat16* __restrict__ obf,
                         const int* __restrict__ smask, int writeAttn)
{
    extern __shared__ char smem[];
    const uint32_t sb = smem_u32(smem);

    const int tid = threadIdx.x;
    const int wid = tid >> 5;
    const int lane = tid & 31;

    const int z = blockIdx.z;
    const int m0 = blockIdx.y * 128;
    const int n0 = blockIdx.x * 128;
    const long Kr = 2L * C;
    const __nv_bfloat16* Ab = A + (long)z * aBatch;
    const __nv_bfloat16* Bb = Bm + (long)z * bBatch;

    const int kc = C >> 6;     // 64-col chunks per segment
    const int nk = 3 * kc;

    const int vr0 = tid >> 3;          // load row base (stride 32)
    const int vc16 = (tid & 7) * 16;   // byte offset in 128B row

#define LDG_STAGE(IT, S)                                                          \
    {                                                                             \
        int _it = (IT);                                                           \
        int _seg = (_it >= 2 * kc) ? 2 : ((_it >= kc) ? 1 : 0);                   \
        int _kl = _it - _seg * kc;                                                \
        long _aC = ((_seg == 1) ? C : 0) + (long)_kl * 64 + (vc16 >> 1);          \
        long _bC = ((_seg == 2) ? C : 0) + (long)_kl * 64 + (vc16 >> 1);          \
        uint32_t _sA = sb + (S) * 32768u;                                         \
        uint32_t _sB = _sA + 16384u;                                              \
        _Pragma("unroll")                                                         \
        for (int i = 0; i < 4; i++) {                                             \
            int r = vr0 + 32 * i;                                                 \
            uint32_t sw = (uint32_t)(r * 128 + (vc16 ^ ((r & 7) << 4)));          \
            cp16(_sA + sw, Ab + (long)(m0 + r) * Kr + _aC);                       \
            cp16(_sB + sw, Bb + (long)(n0 + r) * Kr + _bC);                       \
        }                                                                         \
    }

    // prologue: prefetch stages 0,1 into buffers 0,1 (buffer 2 free)
    LDG_STAGE(0, 0); CP_COMMIT();
    LDG_STAGE(1, 1); CP_COMMIT();

    const int wm = wid & 1;     // 0..1 -> 64 rows
    const int wn = wid >> 1;    // 0..3 -> 32 cols

    float acc[4][4][4] = {};

    const int arow = wm * 64 + (lane & 15);                     // + mt*16
    const int akb = (lane >> 4) * 16;
    const int brow = wn * 32 + (lane & 7) + ((lane >> 4) * 8);  // + ntp*16
    const int bkb = ((lane >> 3) & 1) * 16;

    for (int it = 0; it < nk; it++) {
        // Stage `it` must be complete: after the prefetch issued last
        // iteration, committed groups cover stages 0..it+1, so allowing 1
        // pending group means stage `it` has landed. On the final iteration
        // no prefetch was issued, so 0 pending is the same condition.
        if (it + 1 < nk) cp_wait<1>(); else cp_wait<0>();
        __syncthreads();   // all warps done reading stage it-1; safe to refill its buffer

        const uint32_t stA = sb + (uint32_t)(it % 3) * 32768u;
        const uint32_t stB = stA + 16384u;

        #pragma unroll
        for (int ks = 0; ks < 4; ks++) {
            uint32_t afr[4][4], bfr[2][4];
            #pragma unroll
            for (int mt = 0; mt < 4; mt++) {
                const int row = arow + mt * 16;
                ldsm_x4(afr[mt], stA + row * 128 + ((ks * 32 + akb) ^ ((row & 7) << 4)));
            }
            #pragma unroll
            for (int ntp = 0; ntp < 2; ntp++) {
                const int row = brow + ntp * 16;
                ldsm_x4(bfr[ntp], stB + row * 128 + ((ks * 32 + bkb) ^ ((row & 7) << 4)));
            }
            #pragma unroll
            for (int mt = 0; mt < 4; mt++)
                #pragma unroll
                for (int nt = 0; nt < 4; nt++)
                    mma_bf16(acc[mt][nt], afr[mt], &bfr[nt >> 1][(nt & 1) * 2]);
        }

        // Prefetch stage it+2 into buffer (it+2)%3 == (it-1)%3. The barrier
        // above proved every warp finished stage it-1, so this is race-free.
        if (it + 2 < nk) { LDG_STAGE(it + 2, (it + 2) % 3); CP_COMMIT(); }
    }

    // ---- epilogue ----
    const int er = wm * 64 + (lane >> 2);        // + mt*16 (+8 for c2/c3)
    const int ec = wn * 32 + (lane & 3) * 2;     // + nt*8

    if (EPI == 0) {
        const int Nout = gridDim.x * 128;
        #pragma unroll
        for (int mt = 0; mt < 4; mt++)
            #pragma unroll
            for (int nt = 0; nt < 4; nt++)
                #pragma unroll
                for (int h = 0; h < 2; h++) {
                    const int row = m0 + er + mt * 16 + h * 8;
                    const int col = n0 + ec + nt * 8;
                    float x0 = fmaxf(acc[mt][nt][2 * h], 0.f);
                    float x1 = fmaxf(acc[mt][nt][2 * h + 1], 0.f);
                    __nv_bfloat16 h0, l0, h1, l1;
                    split1(x0, h0, l0); split1(x1, h1, l1);
                    __nv_bfloat16* oh = obf + (long)row * 2 * Nout + col;
                    *reinterpret_cast<__nv_bfloat162*>(oh) = __nv_bfloat162(h0, h1);
                    *reinterpret_cast<__nv_bfloat162*>(oh + Nout) = __nv_bfloat162(l0, l1);
                }
    } else if (EPI == 1) {
        #pragma unroll
        for (int mt = 0; mt < 4; mt++)
            #pragma unroll
            for (int nt = 0; nt < 4; nt++)
                #pragma unroll
                for (int h = 0; h < 2; h++) {
                    const int row = m0 + er + mt * 16 + h * 8;
                    const int col = n0 + ec + nt * 8;
                    float2 v = make_float2(acc[mt][nt][2 * h], acc[mt][nt][2 * h + 1]);
                    *reinterpret_cast<float2*>(out0 + ((long)z * SS + row) * TT + col) = v;
                }
    } else {
        #pragma unroll
        for (int mt = 0; mt < 4; mt++)
            #pragma unroll
            for (int nt = 0; nt < 4; nt++)
                #pragma unroll
                for (int h = 0; h < 2; h++) {
                    const int row = m0 + er + mt * 16 + h * 8;
                    const int col = n0 + ec + nt * 8;
                    const long gs = (long)z * SS + row;
                    const float m = (float)smask[gs];
                    float2 v = make_float2(acc[mt][nt][2 * h], acc[mt][nt][2 * h + 1]);
                    if (writeAttn)
                        *reinterpret_cast<float2*>(out1 + gs * (long)HH + col) = v;
                    float2 vm = make_float2(v.x * m, v.y * m);
                    *reinterpret_cast<float2*>(out0 + gs * (long)(2 * HH) + HH + col) = vm;
                }
    }
#undef LDG_STAGE
}

// ---------------------------------------------------------------------------
// fp32 [R,C] (row-masked) -> split bf16 [R,2C]; optionally also writes the
// masked fp32 row into out_cat[row, 0:C] (cat first half, stride 2C).
// ---------------------------------------------------------------------------
__launch_bounds__(256)
__global__ void split_mask(const float* __restrict__ in, const int* __restrict__ mask,
                           __nv_bfloat16* __restrict__ out, float* __restrict__ cat,
                           int R, int C)
{
    const long idx = (long)blockIdx.x * blockDim.x + threadIdx.x;  // float4 units
    const long total = (long)R * C / 4;
    if (idx >= total) return;
    const long row = idx / (C / 4);
    const int c4 = (int)(idx % (C / 4));
    const float m = mask ? (float)mask[row] : 1.0f;
    float4 v = reinterpret_cast<const float4*>(in)[idx];
    v.x *= m; v.y *= m; v.z *= m; v.w *= m;
    __nv_bfloat16 h0, l0, h1, l1, h2, l2, h3, l3;
    split1(v.x, h0, l0); split1(v.y, h1, l1); split1(v.z, h2, l2); split1(v.w, h3, l3);
    __nv_bfloat16* oh = out + row * 2L * C + c4 * 4;
    __nv_bfloat16* ol = oh + C;
    reinterpret_cast<__nv_bfloat162*>(oh)[0] = __nv_bfloat162(h0, h1);
    reinterpret_cast<__nv_bfloat162*>(oh)[1] = __nv_bfloat162(h2, h3);
    reinterpret_cast<__nv_bfloat162*>(ol)[0] = __nv_bfloat162(l0, l1);
    reinterpret_cast<__nv_bfloat162*>(ol)[1] = __nv_bfloat162(l2, l3);
    if (cat)
        reinterpret_cast<float4*>(cat)[row * (long)(2 * C / 4) + c4] = v;
}

// ---------------------------------------------------------------------------
// V^T split: O[b,h,t] = split(V[b,t,h]);  O layout [B, H, 2T]
// ---------------------------------------------------------------------------
__global__ void vT_split(const float* __restrict__ V, __nv_bfloat16* __restrict__ O)
{
    __shared__ float tile[32][33];
    const int b = blockIdx.z;
    const int t0 = blockIdx.x * 32, h0 = blockIdx.y * 32;
    const int tx = threadIdx.x, ty = threadIdx.y;  // 32 x 8
    #pragma unroll
    for (int i = 0; i < 32; i += 8)
        tile[ty + i][tx] = V[((long)b * TT + t0 + ty + i) * HH + h0 + tx];
    __syncthreads();
    #pragma unroll
    for (int i = 0; i < 32; i += 8) {
        const int h = h0 + ty + i, t = t0 + tx;
        __nv_bfloat16 hh, ll;
        split1(tile[tx][ty + i], hh, ll);
        const long base = ((long)b * HH + h) * (2L * TT) + t;
        O[base] = hh; O[base + TT] = ll;
    }
}

// ---------------------------------------------------------------------------
// Row softmax over T=512 + split-bf16 probs write.
// ---------------------------------------------------------------------------
__launch_bounds__(128)
__global__ void softmax_split(const float* __restrict__ logits, __nv_bfloat16* __restrict__ P2)
{
    const long row = blockIdx.x;
    const float* p = logits + row * TT;
    const int tid = threadIdx.x;
    const int warp = tid >> 5, lane = tid & 31;

    float v[4];
    #pragma unroll
    for (int i = 0; i < 4; i++) v[i] = p[tid + 128 * i];

    float mx = fmaxf(fmaxf(v[0], v[1]), fmaxf(v[2], v[3]));
    #pragma unroll
    for (int o = 16; o > 0; o >>= 1) mx = fmaxf(mx, __shfl_xor_sync(0xffffffffu, mx, o));
    __shared__ float smx[4];
    if (lane == 0) smx[warp] = mx;
    __syncthreads();
    mx = fmaxf(fmaxf(smx[0], smx[1]), fmaxf(smx[2], smx[3]));

    float sum = 0.f;
    #pragma unroll
    for (int i = 0; i < 4; i++) { v[i] = __expf(v[i] - mx); sum += v[i]; }
    #pragma unroll
    for (int o = 16; o > 0; o >>= 1) sum += __shfl_xor_sync(0xffffffffu, sum, o);
    __shared__ float ssum[4];
    if (lane == 0) ssum[warp] = sum;
    __syncthreads();
    const float inv = 1.0f / (ssum[0] + ssum[1] + ssum[2] + ssum[3]);

    __nv_bfloat16* out = P2 + row * 2L * TT;
    #pragma unroll
    for (int i = 0; i < 4; i++) {
        const int idx = tid + 128 * i;
        __nv_bfloat16 h, l;
        split1(v[i] * inv, h, l);
        out[idx] = h; out[TT + idx] = l;
    }
}

// ---------------------------------------------------------------------------

extern "C" void kernel_launch(void* const* d_in, const int* in_sizes, int n_in,
                              void* d_out, int out_size)
{
    const float* seq   = (const float*)d_in[0];
    const int*   smask = (const int*)d_in[1];
    const float* tgt   = (const float*)d_in[2];
    const int*   tmask = (const int*)d_in[3];
    const float* W     = (const float*)d_in[4];
    float* out = (float*)d_out;

    __nv_bfloat16 *p_seq2, *p_tgt2, *p_W2, *p_seqt2, *p_tgtt2, *p_probs2, *p_vT2;
    float* p_logits;
    cudaGetSymbolAddress((void**)&p_seq2, g_seq2);
    cudaGetSymbolAddress((void**)&p_tgt2, g_tgt2);
    cudaGetSymbolAddress((void**)&p_W2, g_W2);
    cudaGetSymbolAddress((void**)&p_seqt2, g_seqt2);
    cudaGetSymbolAddress((void**)&p_tgtt2, g_tgtt2);
    cudaGetSymbolAddress((void**)&p_logits, g_logits);
    cudaGetSymbolAddress((void**)&p_probs2, g_probs2);
    cudaGetSymbolAddress((void**)&p_vT2, g_vT2);

    const int write_attn = (out_size >= BB * SS * 3 * HH) ? 1 : 0;
    float* out_attn = out + (size_t)BB * SS * 2 * HH;

    const int SMEM_DYN = 3 * 32768;  // 98304 -> 2 CTAs/SM
    cudaFuncSetAttribute(gemm_mma<0>, cudaFuncAttributeMaxDynamicSharedMemorySize, SMEM_DYN);
    cudaFuncSetAttribute(gemm_mma<1>, cudaFuncAttributeMaxDynamicSharedMemorySize, SMEM_DYN);
    cudaFuncSetAttribute(gemm_mma<2>, cudaFuncAttributeMaxDynamicSharedMemorySize, SMEM_DYN);

    // 0) operand conversions (seq variant also writes cat first half)
    split_mask<<<(BB * SS * HH / 4 + 255) / 256, 256>>>(seq, smask, p_seq2, out, BB * SS, HH);
    split_mask<<<(BB * TT * HH / 4 + 255) / 256, 256>>>(tgt, tmask, p_tgt2, nullptr, BB * TT, HH);
    split_mask<<<(HH * HH / 4 + 255) / 256, 256>>>(W, nullptr, p_W2, nullptr, HH, HH);
    vT_split<<<dim3(TT / 32, HH / 32, BB), dim3(32, 8)>>>(tgt, p_vT2);

    // 1) seq_t = relu((seq*sm) @ W^T)  -> split bf16
    gemm_mma<0><<<dim3(HH / 128, (BB * SS) / 128, 1), 256, SMEM_DYN>>>(
        p_seq2, p_W2, 0, 0, HH, nullptr, nullptr, p_seqt2, nullptr, 0);

    // 2) tgt_t = relu((tgt*tm) @ W^T)  -> split bf16
    gemm_mma<0><<<dim3(HH / 128, (BB * TT) / 128, 1), 256, SMEM_DYN>>>(
        p_tgt2, p_W2, 0, 0, HH, nullptr, nullptr, p_tgtt2, nullptr, 0);

    // 3) logits[b] = seq_t[b] @ tgt_t[b]^T  -> fp32
    gemm_mma<1><<<dim3(TT / 128, SS / 128, BB), 256, SMEM_DYN>>>(
        p_seqt2, p_tgtt2, (long)SS * 2 * HH, (long)TT * 2 * HH, HH,
        p_logits, nullptr, nullptr, nullptr, 0);

    // 4) softmax + split
    softmax_split<<<BB * SS, 128>>>(p_logits, p_probs2);

    // 5) attn_out = P @ V^T-split, fused cat/attn epilogue
    gemm_mma<2><<<dim3(HH / 128, SS / 128, BB), 256, SMEM_DYN>>>(
        p_probs2, p_vT2, (long)SS * 2 * TT, (long)HH * 2 * TT, TT,
        out, out_attn, nullptr, smask, write_attn);
}